// round 4
// baseline (speedup 1.0000x reference)
#include <cuda_runtime.h>
#include <cstdint>

// ---------------------------------------------------------------------------
// VectorQuantizerEMA on GB300 (sm_103a)
// B=64, D=128, T=2048, K=1024, N=B*T=131072
//
// Output layout (f32, concatenated in reference return order):
//   [0, 16777216)            out[b,d,t]  (straight-through quantized)
//   [16777216]               loss_commit
//   [16777217]               loss_vq
//   [16777218, 16908290)     idx (as float)
//   [16908290, 17039362)     new_embeddings [K, D]
//
// Argmin replicates the reference's fp32 rounding structure:
//   dist = fl32( fl32(|x|^2 + |e|^2) - 2*(x.e) ), ties -> lowest index.
// ---------------------------------------------------------------------------

#define B_   64
#define D_   128
#define T_   2048
#define K_   1024
#define N_   (B_ * T_)          // 131072
#define DT_  (D_ * T_)          // 262144
#define KD_  (K_ * D_)          // 131072

#define OUT_ELEMS   16777216
#define LOSS_OFF    16777216
#define IDX_OFF     16777218
#define EMB_OFF     16908290

#define D1F   ((float)(1.0 - 0.99))          // 1 - DECAY (== 1 - DECAY**COUNTER)
#define EPSF  1e-5f
#define KEPSF ((float)(1024 * 1e-5))

// -------- device-global scratch (no allocation allowed) --------
__device__ float  g_Et[D_ * K_];      // E transposed [D][K]
__device__ float  g_enorm[K_];        // fl32( exact |e_k|^2 )
__device__ float  g_dw[K_ * D_];      // scatter sums
__device__ float  g_counts[K_];
__device__ float  g_cs[K_];
__device__ double g_loss;

// -------- packed f32x2 helpers (Blackwell PTX) --------
#define FMA_X2(d, a, b) \
    asm("fma.rn.f32x2 %0, %1, %2, %0;" : "+l"(d) : "l"(a), "l"(b))
#define PACK_DUP(d, f) \
    asm("mov.b64 %0, {%1, %1};" : "=l"(d) : "f"(f))
#define UNPACK_X2(lo, hi, v) \
    asm("mov.b64 {%0, %1}, %2;" : "=f"(lo), "=f"(hi) : "l"(v))

// ---------------------------------------------------------------------------
// K0: build E^T and |e|^2 (fp64-exact, rounded to fp32). 1024 blocks x 128
// ---------------------------------------------------------------------------
__global__ void vq_prep(const float* __restrict__ E) {
    int k = blockIdx.x;
    int d = threadIdx.x;
    float v = E[k * D_ + d];
    g_Et[d * K_ + k] = v;
    double s = (double)v * (double)v;
    #pragma unroll
    for (int o = 16; o > 0; o >>= 1) s += __shfl_xor_sync(0xffffffffu, s, o);
    __shared__ double ws[4];
    if ((d & 31) == 0) ws[d >> 5] = s;
    __syncthreads();
    if (d == 0) g_enorm[k] = (float)((ws[0] + ws[1]) + (ws[2] + ws[3]));
}

// ---------------------------------------------------------------------------
// K1: fused distance GEMM + argmin + quantized-output + dw/counts/loss
// grid = (T/128, B) = (16, 64), 256 threads
// Tile: 128 tokens x 128 codes, loop 8 code-tiles; D chunked by 16.
// Thread (ty,tx) owns 8 tokens x 8 codes; codes packed in f32x2 pairs.
// ---------------------------------------------------------------------------
__global__ __launch_bounds__(256) void vq_main(
    const float* __restrict__ x,
    const float* __restrict__ E,
    float* __restrict__ out_q,     // d_out + 0
    float* __restrict__ out_idx)   // d_out + IDX_OFF
{
    const int b  = blockIdx.y;
    const int t0 = blockIdx.x * 128;
    const int tid = threadIdx.x;
    const int tx = tid & 15;       // code group
    const int ty = tid >> 4;       // token group

    extern __shared__ float sm[];
    float* xs      = sm;                      // [128 d][128 t]  16384
    float* es      = xs + 16384;              // [16 dd][128 k]   2048
    float* enorm_s = es + 2048;               // [1024]           1024
    float* red_v   = enorm_s + 1024;          // [128][16]        2048
    int*   red_i   = (int*)(red_v + 2048);    // [128][16]        2048
    int*   idx_s   = red_i + 2048;            // [128]             128
    float* As      = (float*)(idx_s + 128);   // [128] |x_t|^2     128

    // ---- stage full x tile (coalesced along t) ----
    const float* xb = x + (size_t)b * DT_ + t0;
    #pragma unroll
    for (int r = 0; r < 64; r++) {
        int e = tid + r * 256;
        int d = e >> 7, t = e & 127;
        xs[e] = xb[d * T_ + t];
    }
    for (int i = tid; i < K_; i += 256) enorm_s[i] = g_enorm[i];
    __syncthreads();

    // ---- per-token |x|^2 (fp64-exact -> fp32) ----
    if (tid < 128) {
        double a = 0.0;
        #pragma unroll 8
        for (int d = 0; d < 128; d++) {
            float xv = xs[d * 128 + tid];
            a += (double)xv * (double)xv;
        }
        As[tid] = (float)a;
    }
    __syncthreads();

    float a8[8];
    #pragma unroll
    for (int i = 0; i < 8; i++) a8[i] = As[ty * 8 + i];

    float rmin[8];
    int   ridx[8];
    #pragma unroll
    for (int i = 0; i < 8; i++) { rmin[i] = 3.4e38f; ridx[i] = 0; }

    for (int ct = 0; ct < 8; ct++) {
        unsigned long long acc[8][4];
        #pragma unroll
        for (int i = 0; i < 8; i++)
            #pragma unroll
            for (int j = 0; j < 4; j++) acc[i][j] = 0ULL;

        for (int dc = 0; dc < 8; dc++) {
            __syncthreads();
            #pragma unroll
            for (int r = 0; r < 8; r++) {
                int e = tid + r * 256;
                int dd = e >> 7, kk = e & 127;
                es[e] = g_Et[(dc * 16 + dd) * K_ + ct * 128 + kk];
            }
            __syncthreads();

            #pragma unroll
            for (int dd = 0; dd < 16; dd++) {
                const float4* ar =
                    (const float4*)&xs[(dc * 16 + dd) * 128 + ty * 8];
                float4 a0 = ar[0];
                float4 a1 = ar[1];
                const unsigned long long* br =
                    (const unsigned long long*)&es[dd * 128 + tx * 8];
                unsigned long long b0 = br[0], b1 = br[1],
                                   b2 = br[2], b3 = br[3];
                float av[8] = {a0.x, a0.y, a0.z, a0.w,
                               a1.x, a1.y, a1.z, a1.w};
                #pragma unroll
                for (int i = 0; i < 8; i++) {
                    unsigned long long ad;
                    PACK_DUP(ad, av[i]);
                    FMA_X2(acc[i][0], ad, b0);
                    FMA_X2(acc[i][1], ad, b1);
                    FMA_X2(acc[i][2], ad, b2);
                    FMA_X2(acc[i][3], ad, b3);
                }
            }
        }

        // ---- fold into running argmin, replicating reference rounding:
        //      dist = fl32( fl32(A + B_k) - 2*s_k ), strict < keeps lowest idx
        #pragma unroll
        for (int i = 0; i < 8; i++) {
            #pragma unroll
            for (int jp = 0; jp < 4; jp++) {
                float s0, s1;
                UNPACK_X2(s0, s1, acc[i][jp]);
                int col = ct * 128 + tx * 8 + jp * 2;
                float ab0 = __fadd_rn(a8[i], enorm_s[col]);
                float ab1 = __fadd_rn(a8[i], enorm_s[col + 1]);
                float v0 = __fadd_rn(ab0, -2.0f * s0);
                float v1 = __fadd_rn(ab1, -2.0f * s1);
                if (v0 < rmin[i]) { rmin[i] = v0; ridx[i] = col; }
                if (v1 < rmin[i]) { rmin[i] = v1; ridx[i] = col + 1; }
            }
        }
    }

    // ---- cross-thread argmin reduction (lowest index on exact tie) ----
    __syncthreads();
    #pragma unroll
    for (int i = 0; i < 8; i++) {
        int t = ty * 8 + i;
        red_v[t * 16 + tx] = rmin[i];
        red_i[t * 16 + tx] = ridx[i];
    }
    __syncthreads();
    if (tid < 128) {
        float best = red_v[tid * 16];
        int   bi   = red_i[tid * 16];
        #pragma unroll
        for (int s = 1; s < 16; s++) {
            float v = red_v[tid * 16 + s];
            int  ii = red_i[tid * 16 + s];
            if (v < best || (v == best && ii < bi)) { best = v; bi = ii; }
        }
        idx_s[tid] = bi;
        out_idx[b * T_ + t0 + tid] = (float)bi;
        atomicAdd(&g_counts[bi], 1.0f);
    }
    __syncthreads();

    // ---- epilogue: straight-through output, dw scatter, loss ----
    const int t   = tid & 127;           // fixed per thread -> coalesced stores
    const int d0  = tid >> 7;
    const int myk = idx_s[t];
    const float* erow = E + myk * D_;
    float* ob = out_q + (size_t)b * DT_ + t0 + t;
    float* dwr = &g_dw[myk * D_];
    float lsum = 0.0f;
    #pragma unroll 4
    for (int r = 0; r < 64; r++) {
        int d = d0 + 2 * r;
        float xv = xs[d * 128 + t];
        float ev = erow[d];
        // replicate ref: q_st = xt + (quantized - xt), elementwise fp32
        ob[(size_t)d * T_] = __fadd_rn(xv, __fsub_rn(ev, xv));
        atomicAdd(&dwr[d], xv);
        float df = xv - ev;
        lsum += df * df;
    }
    #pragma unroll
    for (int o = 16; o > 0; o >>= 1)
        lsum += __shfl_xor_sync(0xffffffffu, lsum, o);
    if ((tid & 31) == 0) red_v[tid >> 5] = lsum;
    __syncthreads();
    if (tid == 0) {
        float s = 0.0f;
        #pragma unroll
        for (int w = 0; w < 8; w++) s += red_v[w];
        atomicAdd(&g_loss, (double)s);
    }
}

// ---------------------------------------------------------------------------
// K3a: cluster-size EMA + Laplace smoothing + losses.  1 block, 1024 threads
// ---------------------------------------------------------------------------
__global__ void vq_stats(const float* __restrict__ ema_c,
                         float* __restrict__ out_loss) {
    int k = threadIdx.x;
    float c   = g_counts[k];
    float ema = ema_c[k];
    float hid = ema - (ema - c) * D1F;
    float avg = hid / D1F;
    __shared__ float sred[1024];
    sred[k] = avg;
    __syncthreads();
    for (int o = 512; o > 0; o >>= 1) {
        if (k < o) sred[k] += sred[k + o];
        __syncthreads();
    }
    float n = sred[0];
    g_cs[k] = (avg + EPSF) / (n + KEPSF) * n;
    if (k == 0) {
        float mse = (float)(g_loss / 16777216.0);
        out_loss[0] = 0.25f * mse;   // loss_commit
        out_loss[1] = mse;           // loss_vq
    }
}

// ---------------------------------------------------------------------------
// K3b: new_embeddings = avg_dw / cs.  512 blocks x 256
// ---------------------------------------------------------------------------
__global__ void vq_emb(const float* __restrict__ ema_dw,
                       float* __restrict__ out_emb) {
    int e = blockIdx.x * 256 + threadIdx.x;   // < 131072
    int k = e >> 7;
    float dwv = g_dw[e];
    float ema = ema_dw[e];
    float hid = ema - (ema - dwv) * D1F;
    float avg = hid / D1F;
    out_emb[e] = avg / g_cs[k];
}

// ---------------------------------------------------------------------------
extern "C" void kernel_launch(void* const* d_in, const int* in_sizes, int n_in,
                              void* d_out, int out_size) {
    const float* x      = (const float*)d_in[0];
    const float* E      = (const float*)d_in[1];
    const float* ema_dw = (const float*)d_in[2];
    const float* ema_c  = (const float*)d_in[3];
    float* out = (float*)d_out;

    void *p_dw = nullptr, *p_cnt = nullptr, *p_loss = nullptr;
    cudaGetSymbolAddress(&p_dw, g_dw);
    cudaGetSymbolAddress(&p_cnt, g_counts);
    cudaGetSymbolAddress(&p_loss, g_loss);
    cudaMemsetAsync(p_dw, 0, K_ * D_ * sizeof(float));
    cudaMemsetAsync(p_cnt, 0, K_ * sizeof(float));
    cudaMemsetAsync(p_loss, 0, sizeof(double));

    vq_prep<<<K_, 128>>>(E);

    const int smem = 95232;
    cudaFuncSetAttribute(vq_main, cudaFuncAttributeMaxDynamicSharedMemorySize,
                         smem);
    dim3 grid(T_ / 128, B_);
    vq_main<<<grid, 256, smem>>>(x, E, out, out + IDX_OFF);

    vq_stats<<<1, 1024>>>(ema_c, out + LOSS_OFF);
    vq_emb<<<KD_ / 256, 256>>>(ema_dw, out + EMB_OFF);
}

// round 5
// speedup vs baseline: 1.1978x; 1.1978x over previous
#include <cuda_runtime.h>
#include <cstdint>

// ---------------------------------------------------------------------------
// VectorQuantizerEMA on GB300 (sm_103a)
// B=64, D=128, T=2048, K=1024, N=B*T=131072
//
// Output layout (f32, concatenated in reference return order):
//   [0, 16777216)            out[b,d,t]  (straight-through quantized)
//   [16777216]               loss_commit
//   [16777217]               loss_vq
//   [16777218, 16908290)     idx (as float)
//   [16908290, 17039362)     new_embeddings [K, D]
//
// Argmin replicates the reference's fp32 rounding structure:
//   dist = fl32( fl32(|x|^2 + |e|^2) - 2*(x.e) ), ties -> lowest index.
// R5: scheduling-only changes vs the passing R4 kernel (bit-identical math):
//   - __launch_bounds__(256,2) -> 2 CTAs/SM
//   - register-prefetch of next E-tile chunk (hides LDG latency)
//   - 2 duplicate vq_prep launches so ncu -s 5 captures vq_main
// ---------------------------------------------------------------------------

#define B_   64
#define D_   128
#define T_   2048
#define K_   1024
#define N_   (B_ * T_)          // 131072
#define DT_  (D_ * T_)          // 262144
#define KD_  (K_ * D_)          // 131072

#define OUT_ELEMS   16777216
#define LOSS_OFF    16777216
#define IDX_OFF     16777218
#define EMB_OFF     16908290

#define D1F   ((float)(1.0 - 0.99))          // 1 - DECAY (== 1 - DECAY**COUNTER)
#define EPSF  1e-5f
#define KEPSF ((float)(1024 * 1e-5))

// -------- device-global scratch (no allocation allowed) --------
__device__ float  g_Et[D_ * K_];      // E transposed [D][K]
__device__ float  g_enorm[K_];        // fl32( exact |e_k|^2 )
__device__ float  g_dw[K_ * D_];      // scatter sums
__device__ float  g_counts[K_];
__device__ float  g_cs[K_];
__device__ double g_loss;

// -------- packed f32x2 helpers (Blackwell PTX) --------
#define FMA_X2(d, a, b) \
    asm("fma.rn.f32x2 %0, %1, %2, %0;" : "+l"(d) : "l"(a), "l"(b))
#define PACK_DUP(d, f) \
    asm("mov.b64 %0, {%1, %1};" : "=l"(d) : "f"(f))
#define UNPACK_X2(lo, hi, v) \
    asm("mov.b64 {%0, %1}, %2;" : "=f"(lo), "=f"(hi) : "l"(v))

// ---------------------------------------------------------------------------
// K0: build E^T and |e|^2 (fp64-exact, rounded to fp32). 1024 blocks x 128
// (idempotent: also launched twice extra to align ncu skip-count on vq_main)
// ---------------------------------------------------------------------------
__global__ void vq_prep(const float* __restrict__ E) {
    int k = blockIdx.x;
    int d = threadIdx.x;
    float v = E[k * D_ + d];
    g_Et[d * K_ + k] = v;
    double s = (double)v * (double)v;
    #pragma unroll
    for (int o = 16; o > 0; o >>= 1) s += __shfl_xor_sync(0xffffffffu, s, o);
    __shared__ double ws[4];
    if ((d & 31) == 0) ws[d >> 5] = s;
    __syncthreads();
    if (d == 0) g_enorm[k] = (float)((ws[0] + ws[1]) + (ws[2] + ws[3]));
}

// ---------------------------------------------------------------------------
// K1: fused distance GEMM + argmin + quantized-output + dw/counts/loss
// grid = (T/128, B) = (16, 64), 256 threads, 2 CTAs/SM
// Tile: 128 tokens x 128 codes, loop 8 code-tiles; D chunked by 16 with
// register prefetch of the next chunk. Thread (ty,tx) owns 8 tokens x 8
// codes; codes packed in f32x2 pairs. Accumulation order identical to R4.
// ---------------------------------------------------------------------------
__global__ __launch_bounds__(256, 2) void vq_main(
    const float* __restrict__ x,
    const float* __restrict__ E,
    float* __restrict__ out_q,     // d_out + 0
    float* __restrict__ out_idx)   // d_out + IDX_OFF
{
    const int b  = blockIdx.y;
    const int t0 = blockIdx.x * 128;
    const int tid = threadIdx.x;
    const int tx = tid & 15;       // code group
    const int ty = tid >> 4;       // token group

    extern __shared__ float sm[];
    float* xs      = sm;                      // [128 d][128 t]  16384
    float* es      = xs + 16384;              // [16 dd][128 k]   2048
    float* enorm_s = es + 2048;               // [1024]           1024
    float* red_v   = enorm_s + 1024;          // [128][16]        2048
    int*   red_i   = (int*)(red_v + 2048);    // [128][16]        2048
    int*   idx_s   = red_i + 2048;            // [128]             128
    float* As      = (float*)(idx_s + 128);   // [128] |x_t|^2     128

    // ---- stage full x tile (coalesced along t) ----
    const float* xb = x + (size_t)b * DT_ + t0;
    #pragma unroll
    for (int r = 0; r < 64; r++) {
        int e = tid + r * 256;
        int d = e >> 7, t = e & 127;
        xs[e] = xb[d * T_ + t];
    }
    for (int i = tid; i < K_; i += 256) enorm_s[i] = g_enorm[i];
    __syncthreads();

    // ---- per-token |x|^2 (fp64-exact -> fp32) ----
    if (tid < 128) {
        double a = 0.0;
        #pragma unroll 8
        for (int d = 0; d < 128; d++) {
            float xv = xs[d * 128 + tid];
            a += (double)xv * (double)xv;
        }
        As[tid] = (float)a;
    }
    __syncthreads();

    float a8[8];
    #pragma unroll
    for (int i = 0; i < 8; i++) a8[i] = As[ty * 8 + i];

    float rmin[8];
    int   ridx[8];
    #pragma unroll
    for (int i = 0; i < 8; i++) { rmin[i] = 3.4e38f; ridx[i] = 0; }

    // per-thread staging addresses: element e = tid + r*256
    //   dd(e) = (tid>>7) + 2r, kk(e) = tid & 127
    const int kk  = tid & 127;
    const int dd0 = tid >> 7;

    // prefetch chunk (ct=0, dc=0) into registers
    float pf[8];
    #pragma unroll
    for (int r = 0; r < 8; r++)
        pf[r] = g_Et[(0 * 16 + dd0 + 2 * r) * K_ + 0 * 128 + kk];

    for (int ct = 0; ct < 8; ct++) {
        unsigned long long acc[8][4];
        #pragma unroll
        for (int i = 0; i < 8; i++)
            #pragma unroll
            for (int j = 0; j < 4; j++) acc[i][j] = 0ULL;

        for (int dc = 0; dc < 8; dc++) {
            __syncthreads();              // prior compute done reading es
            #pragma unroll
            for (int r = 0; r < 8; r++) es[tid + r * 256] = pf[r];

            // prefetch next chunk (clamped on the very last chunk)
            int ndc = dc + 1, nct = ct;
            if (ndc == 8) { ndc = 0; nct = ct + 1; }
            if (nct == 8) { nct = 0; }    // harmless re-read of chunk 0
            #pragma unroll
            for (int r = 0; r < 8; r++)
                pf[r] = g_Et[(ndc * 16 + dd0 + 2 * r) * K_ + nct * 128 + kk];

            __syncthreads();              // es visible to all warps

            #pragma unroll
            for (int dd = 0; dd < 16; dd++) {
                const float4* ar =
                    (const float4*)&xs[(dc * 16 + dd) * 128 + ty * 8];
                float4 a0 = ar[0];
                float4 a1 = ar[1];
                const unsigned long long* br =
                    (const unsigned long long*)&es[dd * 128 + tx * 8];
                unsigned long long b0 = br[0], b1 = br[1],
                                   b2 = br[2], b3 = br[3];
                float av[8] = {a0.x, a0.y, a0.z, a0.w,
                               a1.x, a1.y, a1.z, a1.w};
                #pragma unroll
                for (int i = 0; i < 8; i++) {
                    unsigned long long ad;
                    PACK_DUP(ad, av[i]);
                    FMA_X2(acc[i][0], ad, b0);
                    FMA_X2(acc[i][1], ad, b1);
                    FMA_X2(acc[i][2], ad, b2);
                    FMA_X2(acc[i][3], ad, b3);
                }
            }
        }

        // ---- fold into running argmin, replicating reference rounding:
        //      dist = fl32( fl32(A + B_k) - 2*s_k ), strict < keeps lowest idx
        #pragma unroll
        for (int i = 0; i < 8; i++) {
            #pragma unroll
            for (int jp = 0; jp < 4; jp++) {
                float s0, s1;
                UNPACK_X2(s0, s1, acc[i][jp]);
                int col = ct * 128 + tx * 8 + jp * 2;
                float ab0 = __fadd_rn(a8[i], enorm_s[col]);
                float ab1 = __fadd_rn(a8[i], enorm_s[col + 1]);
                float v0 = __fadd_rn(ab0, -2.0f * s0);
                float v1 = __fadd_rn(ab1, -2.0f * s1);
                if (v0 < rmin[i]) { rmin[i] = v0; ridx[i] = col; }
                if (v1 < rmin[i]) { rmin[i] = v1; ridx[i] = col + 1; }
            }
        }
    }

    // ---- cross-thread argmin reduction (lowest index on exact tie) ----
    __syncthreads();
    #pragma unroll
    for (int i = 0; i < 8; i++) {
        int t = ty * 8 + i;
        red_v[t * 16 + tx] = rmin[i];
        red_i[t * 16 + tx] = ridx[i];
    }
    __syncthreads();
    if (tid < 128) {
        float best = red_v[tid * 16];
        int   bi   = red_i[tid * 16];
        #pragma unroll
        for (int s = 1; s < 16; s++) {
            float v = red_v[tid * 16 + s];
            int  ii = red_i[tid * 16 + s];
            if (v < best || (v == best && ii < bi)) { best = v; bi = ii; }
        }
        idx_s[tid] = bi;
        out_idx[b * T_ + t0 + tid] = (float)bi;
        atomicAdd(&g_counts[bi], 1.0f);
    }
    __syncthreads();

    // ---- epilogue: straight-through output, dw scatter, loss ----
    const int t   = tid & 127;           // fixed per thread -> coalesced stores
    const int d0  = tid >> 7;
    const int myk = idx_s[t];
    const float* erow = E + myk * D_;
    float* ob = out_q + (size_t)b * DT_ + t0 + t;
    float* dwr = &g_dw[myk * D_];
    float lsum = 0.0f;
    #pragma unroll 4
    for (int r = 0; r < 64; r++) {
        int d = d0 + 2 * r;
        float xv = xs[d * 128 + t];
        float ev = erow[d];
        // replicate ref: q_st = xt + (quantized - xt), elementwise fp32
        ob[(size_t)d * T_] = __fadd_rn(xv, __fsub_rn(ev, xv));
        atomicAdd(&dwr[d], xv);
        float df = xv - ev;
        lsum += df * df;
    }
    #pragma unroll
    for (int o = 16; o > 0; o >>= 1)
        lsum += __shfl_xor_sync(0xffffffffu, lsum, o);
    if ((tid & 31) == 0) red_v[tid >> 5] = lsum;
    __syncthreads();
    if (tid == 0) {
        float s = 0.0f;
        #pragma unroll
        for (int w = 0; w < 8; w++) s += red_v[w];
        atomicAdd(&g_loss, (double)s);
    }
}

// ---------------------------------------------------------------------------
// K3a: cluster-size EMA + Laplace smoothing + losses.  1 block, 1024 threads
// ---------------------------------------------------------------------------
__global__ void vq_stats(const float* __restrict__ ema_c,
                         float* __restrict__ out_loss) {
    int k = threadIdx.x;
    float c   = g_counts[k];
    float ema = ema_c[k];
    float hid = ema - (ema - c) * D1F;
    float avg = hid / D1F;
    __shared__ float sred[1024];
    sred[k] = avg;
    __syncthreads();
    for (int o = 512; o > 0; o >>= 1) {
        if (k < o) sred[k] += sred[k + o];
        __syncthreads();
    }
    float n = sred[0];
    g_cs[k] = (avg + EPSF) / (n + KEPSF) * n;
    if (k == 0) {
        float mse = (float)(g_loss / 16777216.0);
        out_loss[0] = 0.25f * mse;   // loss_commit
        out_loss[1] = mse;           // loss_vq
    }
}

// ---------------------------------------------------------------------------
// K3b: new_embeddings = avg_dw / cs.  512 blocks x 256
// ---------------------------------------------------------------------------
__global__ void vq_emb(const float* __restrict__ ema_dw,
                       float* __restrict__ out_emb) {
    int e = blockIdx.x * 256 + threadIdx.x;   // < 131072
    int k = e >> 7;
    float dwv = g_dw[e];
    float ema = ema_dw[e];
    float hid = ema - (ema - dwv) * D1F;
    float avg = hid / D1F;
    out_emb[e] = avg / g_cs[k];
}

// ---------------------------------------------------------------------------
extern "C" void kernel_launch(void* const* d_in, const int* in_sizes, int n_in,
                              void* d_out, int out_size) {
    const float* x      = (const float*)d_in[0];
    const float* E      = (const float*)d_in[1];
    const float* ema_dw = (const float*)d_in[2];
    const float* ema_c  = (const float*)d_in[3];
    float* out = (float*)d_out;

    void *p_dw = nullptr, *p_cnt = nullptr, *p_loss = nullptr;
    cudaGetSymbolAddress(&p_dw, g_dw);
    cudaGetSymbolAddress(&p_cnt, g_counts);
    cudaGetSymbolAddress(&p_loss, g_loss);
    cudaMemsetAsync(p_dw, 0, K_ * D_ * sizeof(float));
    cudaMemsetAsync(p_cnt, 0, K_ * sizeof(float));
    cudaMemsetAsync(p_loss, 0, sizeof(double));

    // vq_prep is idempotent; the two extra launches place vq_main at kernel
    // position 7 so ncu (-s 5 -c 1) captures the main kernel's profile.
    vq_prep<<<K_, 128>>>(E);
    vq_prep<<<K_, 128>>>(E);
    vq_prep<<<K_, 128>>>(E);

    const int smem = 95232;
    cudaFuncSetAttribute(vq_main, cudaFuncAttributeMaxDynamicSharedMemorySize,
                         smem);
    dim3 grid(T_ / 128, B_);
    vq_main<<<grid, 256, smem>>>(x, E, out, out + IDX_OFF);

    vq_stats<<<1, 1024>>>(ema_c, out + LOSS_OFF);
    vq_emb<<<KD_ / 256, 256>>>(ema_dw, out + EMB_OFF);
}

// round 6
// speedup vs baseline: 1.2906x; 1.0775x over previous
#include <cuda_runtime.h>
#include <cstdint>

// ---------------------------------------------------------------------------
// VectorQuantizerEMA on GB300 (sm_103a)
// B=64, D=128, T=2048, K=1024, N=B*T=131072
//
// Output layout (f32, concatenated in reference return order):
//   [0, 16777216)            out[b,d,t]  (straight-through quantized)
//   [16777216]               loss_commit
//   [16777217]               loss_vq
//   [16777218, 16908290)     idx (as float)
//   [16908290, 17039362)     new_embeddings [K, D]
//
// Argmin replicates the reference's fp32 rounding structure:
//   dist = fl32( fl32(|x|^2 + |e|^2) - 2*(x.e) ), ties -> lowest index.
//
// R6 vs R5 (scheduling/layout only; per-code arithmetic bit-identical):
//   - code ownership remap: thread tx owns pairs {32j+2tx, 32j+2tx+1}
//     -> B-operand LDS.64 is bank-conflict-free (was 4-way conflicted)
//   - double-buffered es tile -> one __syncthreads per dc phase
// ---------------------------------------------------------------------------

#define B_   64
#define D_   128
#define T_   2048
#define K_   1024
#define N_   (B_ * T_)          // 131072
#define DT_  (D_ * T_)          // 262144
#define KD_  (K_ * D_)          // 131072

#define OUT_ELEMS   16777216
#define LOSS_OFF    16777216
#define IDX_OFF     16777218
#define EMB_OFF     16908290

#define D1F   ((float)(1.0 - 0.99))          // 1 - DECAY (== 1 - DECAY**COUNTER)
#define EPSF  1e-5f
#define KEPSF ((float)(1024 * 1e-5))

// -------- device-global scratch (no allocation allowed) --------
__device__ float  g_Et[D_ * K_];      // E transposed [D][K]
__device__ float  g_enorm[K_];        // fl32( exact |e_k|^2 )
__device__ float  g_dw[K_ * D_];      // scatter sums
__device__ float  g_counts[K_];
__device__ float  g_cs[K_];
__device__ double g_loss;

// -------- packed f32x2 helpers (Blackwell PTX) --------
#define FMA_X2(d, a, b) \
    asm("fma.rn.f32x2 %0, %1, %2, %0;" : "+l"(d) : "l"(a), "l"(b))
#define PACK_DUP(d, f) \
    asm("mov.b64 %0, {%1, %1};" : "=l"(d) : "f"(f))
#define UNPACK_X2(lo, hi, v) \
    asm("mov.b64 {%0, %1}, %2;" : "=f"(lo), "=f"(hi) : "l"(v))

// ---------------------------------------------------------------------------
// K0: build E^T and |e|^2 (fp64-exact, rounded to fp32). 1024 blocks x 128
// (idempotent: launched 3x so ncu -s 5 -c 1 lands on vq_main)
// ---------------------------------------------------------------------------
__global__ void vq_prep(const float* __restrict__ E) {
    int k = blockIdx.x;
    int d = threadIdx.x;
    float v = E[k * D_ + d];
    g_Et[d * K_ + k] = v;
    double s = (double)v * (double)v;
    #pragma unroll
    for (int o = 16; o > 0; o >>= 1) s += __shfl_xor_sync(0xffffffffu, s, o);
    __shared__ double ws[4];
    if ((d & 31) == 0) ws[d >> 5] = s;
    __syncthreads();
    if (d == 0) g_enorm[k] = (float)((ws[0] + ws[1]) + (ws[2] + ws[3]));
}

// ---------------------------------------------------------------------------
// K1: fused distance GEMM + argmin + quantized-output + dw/counts/loss
// grid = (T/128, B) = (16, 64), 256 threads, 2 CTAs/SM
// Tile: 128 tokens x 128 codes, 8 code-tiles; D chunked by 16, es tile
// double-buffered with register prefetch. Thread (ty,tx) owns 8 tokens x
// 4 code PAIRS {ct*128 + 32*j + 2*tx, +1}.
// ---------------------------------------------------------------------------
__global__ __launch_bounds__(256, 2) void vq_main(
    const float* __restrict__ x,
    const float* __restrict__ E,
    float* __restrict__ out_q,     // d_out + 0
    float* __restrict__ out_idx)   // d_out + IDX_OFF
{
    const int b  = blockIdx.y;
    const int t0 = blockIdx.x * 128;
    const int tid = threadIdx.x;
    const int tx = tid & 15;       // code group
    const int ty = tid >> 4;       // token group

    extern __shared__ float sm[];
    float* xs      = sm;                      // [128 d][128 t]   16384
    float* es      = xs + 16384;              // 2 x [16][128]     4096
    float* enorm_s = es + 4096;               // [1024]            1024
    float* red_v   = enorm_s + 1024;          // [128][16]         2048
    int*   red_i   = (int*)(red_v + 2048);    // [128][16]         2048
    int*   idx_s   = red_i + 2048;            // [128]              128
    float* As      = (float*)(idx_s + 128);   // [128] |x_t|^2      128

    // ---- stage full x tile (coalesced along t) ----
    const float* xb = x + (size_t)b * DT_ + t0;
    #pragma unroll
    for (int r = 0; r < 64; r++) {
        int e = tid + r * 256;
        int d = e >> 7, t = e & 127;
        xs[e] = xb[d * T_ + t];
    }
    for (int i = tid; i < K_; i += 256) enorm_s[i] = g_enorm[i];
    __syncthreads();

    // ---- per-token |x|^2 (fp64-exact -> fp32) ----
    if (tid < 128) {
        double a = 0.0;
        #pragma unroll 8
        for (int d = 0; d < 128; d++) {
            float xv = xs[d * 128 + tid];
            a += (double)xv * (double)xv;
        }
        As[tid] = (float)a;
    }
    __syncthreads();

    float a8[8];
    #pragma unroll
    for (int i = 0; i < 8; i++) a8[i] = As[ty * 8 + i];

    float rmin[8];
    int   ridx[8];
    #pragma unroll
    for (int i = 0; i < 8; i++) { rmin[i] = 3.4e38f; ridx[i] = 0; }

    // per-thread staging address: element e = tid + r*256 of a 16x128 chunk
    //   dd(e) = (tid>>7) + 2r, kk(e) = tid & 127
    const int kk  = tid & 127;
    const int dd0 = tid >> 7;

    // chunk q (0..63): ct = q>>3, dc = q&7
    // preload chunk 0 into es[buf 0]; prefetch chunk 1 into registers
    float pf[8];
    #pragma unroll
    for (int r = 0; r < 8; r++)
        es[tid + r * 256] = g_Et[(dd0 + 2 * r) * K_ + kk];
    #pragma unroll
    for (int r = 0; r < 8; r++)
        pf[r] = g_Et[((1 & 7) * 16 + dd0 + 2 * r) * K_ + (1 >> 3) * 128 + kk];
    __syncthreads();

    for (int ct = 0; ct < 8; ct++) {
        unsigned long long acc[8][4];
        #pragma unroll
        for (int i = 0; i < 8; i++)
            #pragma unroll
            for (int j = 0; j < 4; j++) acc[i][j] = 0ULL;

        for (int dc = 0; dc < 8; dc++) {
            const int p = ct * 8 + dc;
            float* eb = es + ((p & 1) << 11);          // current buffer
            float* en = es + (((p + 1) & 1) << 11);    // next buffer

            // store previously prefetched chunk (p+1) into the other buffer
            // (safe: everyone passed the sync ending phase p-1, which was the
            //  last reader of that buffer)
            if (p + 1 < 64) {
                #pragma unroll
                for (int r = 0; r < 8; r++) en[tid + r * 256] = pf[r];
                // prefetch chunk p+2 from global
                int q = p + 2 < 64 ? p + 2 : 0;
                int qc = q >> 3, qd = q & 7;
                #pragma unroll
                for (int r = 0; r < 8; r++)
                    pf[r] = g_Et[(qd * 16 + dd0 + 2 * r) * K_ + qc * 128 + kk];
            }

            #pragma unroll
            for (int dd = 0; dd < 16; dd++) {
                const float4* ar =
                    (const float4*)&xs[(dc * 16 + dd) * 128 + ty * 8];
                float4 a0 = ar[0];
                float4 a1 = ar[1];
                // conflict-free: lane tx reads banks {2tx, 2tx+1}
                const unsigned long long* brow =
                    (const unsigned long long*)&eb[dd * 128 + tx * 2];
                unsigned long long b0 = brow[0];       // codes 2tx,2tx+1
                unsigned long long b1 = brow[16];      // +32
                unsigned long long b2 = brow[32];      // +64
                unsigned long long b3 = brow[48];      // +96
                float av[8] = {a0.x, a0.y, a0.z, a0.w,
                               a1.x, a1.y, a1.z, a1.w};
                #pragma unroll
                for (int i = 0; i < 8; i++) {
                    unsigned long long ad;
                    PACK_DUP(ad, av[i]);
                    FMA_X2(acc[i][0], ad, b0);
                    FMA_X2(acc[i][1], ad, b1);
                    FMA_X2(acc[i][2], ad, b2);
                    FMA_X2(acc[i][3], ad, b3);
                }
            }
            __syncthreads();   // next-buffer writes visible; eb free for reuse
        }

        // ---- fold into running argmin, replicating reference rounding:
        //      dist = fl32( fl32(A + B_k) - 2*s_k ), strict < keeps lowest idx
        #pragma unroll
        for (int jp = 0; jp < 4; jp++) {
            int col = ct * 128 + jp * 32 + tx * 2;
            float2 en2 = *(const float2*)&enorm_s[col];
            #pragma unroll
            for (int i = 0; i < 8; i++) {
                float s0, s1;
                UNPACK_X2(s0, s1, acc[i][jp]);
                float ab0 = __fadd_rn(a8[i], en2.x);
                float ab1 = __fadd_rn(a8[i], en2.y);
                float v0 = __fadd_rn(ab0, -2.0f * s0);
                float v1 = __fadd_rn(ab1, -2.0f * s1);
                if (v0 < rmin[i]) { rmin[i] = v0; ridx[i] = col; }
                if (v1 < rmin[i]) { rmin[i] = v1; ridx[i] = col + 1; }
            }
        }
    }

    // ---- cross-thread argmin reduction (lowest index on exact tie) ----
    __syncthreads();
    #pragma unroll
    for (int i = 0; i < 8; i++) {
        int t = ty * 8 + i;
        red_v[t * 16 + tx] = rmin[i];
        red_i[t * 16 + tx] = ridx[i];
    }
    __syncthreads();
    if (tid < 128) {
        float best = red_v[tid * 16];
        int   bi   = red_i[tid * 16];
        #pragma unroll
        for (int s = 1; s < 16; s++) {
            float v = red_v[tid * 16 + s];
            int  ii = red_i[tid * 16 + s];
            if (v < best || (v == best && ii < bi)) { best = v; bi = ii; }
        }
        idx_s[tid] = bi;
        out_idx[b * T_ + t0 + tid] = (float)bi;
        atomicAdd(&g_counts[bi], 1.0f);
    }
    __syncthreads();

    // ---- epilogue: straight-through output, dw scatter, loss ----
    const int t   = tid & 127;           // fixed per thread -> coalesced stores
    const int d0  = tid >> 7;
    const int myk = idx_s[t];
    const float* erow = E + myk * D_;
    float* ob = out_q + (size_t)b * DT_ + t0 + t;
    float* dwr = &g_dw[myk * D_];
    float lsum = 0.0f;
    #pragma unroll 4
    for (int r = 0; r < 64; r++) {
        int d = d0 + 2 * r;
        float xv = xs[d * 128 + t];
        float ev = erow[d];
        // replicate ref: q_st = xt + (quantized - xt), elementwise fp32
        ob[(size_t)d * T_] = __fadd_rn(xv, __fsub_rn(ev, xv));
        atomicAdd(&dwr[d], xv);
        float df = xv - ev;
        lsum += df * df;
    }
    #pragma unroll
    for (int o = 16; o > 0; o >>= 1)
        lsum += __shfl_xor_sync(0xffffffffu, lsum, o);
    if ((tid & 31) == 0) red_v[tid >> 5] = lsum;
    __syncthreads();
    if (tid == 0) {
        float s = 0.0f;
        #pragma unroll
        for (int w = 0; w < 8; w++) s += red_v[w];
        atomicAdd(&g_loss, (double)s);
    }
}

// ---------------------------------------------------------------------------
// K3a: cluster-size EMA + Laplace smoothing + losses.  1 block, 1024 threads
// ---------------------------------------------------------------------------
__global__ void vq_stats(const float* __restrict__ ema_c,
                         float* __restrict__ out_loss) {
    int k = threadIdx.x;
    float c   = g_counts[k];
    float ema = ema_c[k];
    float hid = ema - (ema - c) * D1F;
    float avg = hid / D1F;
    __shared__ float sred[1024];
    sred[k] = avg;
    __syncthreads();
    for (int o = 512; o > 0; o >>= 1) {
        if (k < o) sred[k] += sred[k + o];
        __syncthreads();
    }
    float n = sred[0];
    g_cs[k] = (avg + EPSF) / (n + KEPSF) * n;
    if (k == 0) {
        float mse = (float)(g_loss / 16777216.0);
        out_loss[0] = 0.25f * mse;   // loss_commit
        out_loss[1] = mse;           // loss_vq
    }
}

// ---------------------------------------------------------------------------
// K3b: new_embeddings = avg_dw / cs.  512 blocks x 256
// ---------------------------------------------------------------------------
__global__ void vq_emb(const float* __restrict__ ema_dw,
                       float* __restrict__ out_emb) {
    int e = blockIdx.x * 256 + threadIdx.x;   // < 131072
    int k = e >> 7;
    float dwv = g_dw[e];
    float ema = ema_dw[e];
    float hid = ema - (ema - dwv) * D1F;
    float avg = hid / D1F;
    out_emb[e] = avg / g_cs[k];
}

// ---------------------------------------------------------------------------
extern "C" void kernel_launch(void* const* d_in, const int* in_sizes, int n_in,
                              void* d_out, int out_size) {
    const float* x      = (const float*)d_in[0];
    const float* E      = (const float*)d_in[1];
    const float* ema_dw = (const float*)d_in[2];
    const float* ema_c  = (const float*)d_in[3];
    float* out = (float*)d_out;

    void *p_dw = nullptr, *p_cnt = nullptr, *p_loss = nullptr;
    cudaGetSymbolAddress(&p_dw, g_dw);
    cudaGetSymbolAddress(&p_cnt, g_counts);
    cudaGetSymbolAddress(&p_loss, g_loss);
    cudaMemsetAsync(p_dw, 0, K_ * D_ * sizeof(float));
    cudaMemsetAsync(p_cnt, 0, K_ * sizeof(float));
    cudaMemsetAsync(p_loss, 0, sizeof(double));

    // vq_prep is idempotent; extra launches keep vq_main at ncu's -s 5 slot.
    vq_prep<<<K_, 128>>>(E);
    vq_prep<<<K_, 128>>>(E);
    vq_prep<<<K_, 128>>>(E);

    const int smem = 103424;
    cudaFuncSetAttribute(vq_main, cudaFuncAttributeMaxDynamicSharedMemorySize,
                         smem);
    dim3 grid(T_ / 128, B_);
    vq_main<<<grid, 256, smem>>>(x, E, out, out + IDX_OFF);

    vq_stats<<<1, 1024>>>(ema_c, out + LOSS_OFF);
    vq_emb<<<KD_ / 256, 256>>>(ema_dw, out + EMB_OFF);
}

// round 7
// speedup vs baseline: 1.3247x; 1.0264x over previous
#include <cuda_runtime.h>
#include <cstdint>

// ---------------------------------------------------------------------------
// VectorQuantizerEMA on GB300 (sm_103a)
// B=64, D=128, T=2048, K=1024, N=B*T=131072
//
// Output layout (f32, concatenated in reference return order):
//   [0, 16777216)            out[b,d,t]  (straight-through quantized)
//   [16777216]               loss_commit
//   [16777217]               loss_vq
//   [16777218, 16908290)     idx (as float)
//   [16908290, 17039362)     new_embeddings [K, D]
//
// Argmin replicates the reference's fp32 rounding structure:
//   dist = fl32( fl32(|x|^2 + |e|^2) - 2*(x.e) ), ties -> lowest index.
//
// R7 vs R6 (register diet; per-code FMA chains bit-identical):
//   - cp.async staging for x tile, enorm, and E chunks (pf[] regs gone)
//   - running argmin kept as packed u64 (valbits<<32 | col) in smem
//     (distances > 0 so float-bit ordering == value ordering; packed min
//      == min value then lowest index — identical tie semantics)
// ---------------------------------------------------------------------------

#define B_   64
#define D_   128
#define T_   2048
#define K_   1024
#define DT_  (D_ * T_)          // 262144
#define KD_  (K_ * D_)          // 131072

#define LOSS_OFF    16777216
#define IDX_OFF     16777218
#define EMB_OFF     16908290

#define D1F   ((float)(1.0 - 0.99))
#define EPSF  1e-5f
#define KEPSF ((float)(1024 * 1e-5))

// -------- device-global scratch (no allocation allowed) --------
__device__ float  g_Et[D_ * K_];      // E transposed [D][K]
__device__ float  g_enorm[K_];        // fl32( exact |e_k|^2 )
__device__ float  g_dw[K_ * D_];      // scatter sums
__device__ float  g_counts[K_];
__device__ float  g_cs[K_];
__device__ double g_loss;

// -------- packed f32x2 helpers (Blackwell PTX) --------
#define FMA_X2(d, a, b) \
    asm("fma.rn.f32x2 %0, %1, %2, %0;" : "+l"(d) : "l"(a), "l"(b))
#define PACK_DUP(d, f) \
    asm("mov.b64 %0, {%1, %1};" : "=l"(d) : "f"(f))
#define UNPACK_X2(lo, hi, v) \
    asm("mov.b64 {%0, %1}, %2;" : "=f"(lo), "=f"(hi) : "l"(v))

// -------- cp.async helpers --------
#define CP_ASYNC16(dst_u32, src_ptr) \
    asm volatile("cp.async.cg.shared.global [%0], [%1], 16;" \
                 :: "r"(dst_u32), "l"(src_ptr) : "memory")
#define CP_COMMIT() asm volatile("cp.async.commit_group;" ::: "memory")
#define CP_WAIT0()  asm volatile("cp.async.wait_group 0;" ::: "memory")

__device__ __forceinline__ uint32_t smem_u32(const void* p) {
    return (uint32_t)__cvta_generic_to_shared(p);
}

// ---------------------------------------------------------------------------
// K0: build E^T and |e|^2 (fp64-exact, rounded to fp32). 1024 blocks x 128
// (idempotent: launched 3x so ncu -s 5 -c 1 lands on vq_main)
// ---------------------------------------------------------------------------
__global__ void vq_prep(const float* __restrict__ E) {
    int k = blockIdx.x;
    int d = threadIdx.x;
    float v = E[k * D_ + d];
    g_Et[d * K_ + k] = v;
    double s = (double)v * (double)v;
    #pragma unroll
    for (int o = 16; o > 0; o >>= 1) s += __shfl_xor_sync(0xffffffffu, s, o);
    __shared__ double ws[4];
    if ((d & 31) == 0) ws[d >> 5] = s;
    __syncthreads();
    if (d == 0) g_enorm[k] = (float)((ws[0] + ws[1]) + (ws[2] + ws[3]));
}

// ---------------------------------------------------------------------------
// K1: fused distance GEMM + argmin + quantized-output + dw/counts/loss
// grid = (16, 64), 256 threads, 2 CTAs/SM.
// Tile 128 tokens x 128 codes, 8 code-tiles; D chunked by 16; es tile
// double-buffered, filled by cp.async. Thread (ty,tx) owns 8 tokens x
// 4 code PAIRS {ct*128 + 32*j + 2*tx, +1} (conflict-free LDS.64).
// ---------------------------------------------------------------------------
__global__ __launch_bounds__(256, 2) void vq_main(
    const float* __restrict__ x,
    const float* __restrict__ E,
    float* __restrict__ out_q,     // d_out + 0
    float* __restrict__ out_idx)   // d_out + IDX_OFF
{
    const int b  = blockIdx.y;
    const int t0 = blockIdx.x * 128;
    const int tid = threadIdx.x;
    const int tx = tid & 15;       // code group
    const int ty = tid >> 4;       // token group

    extern __shared__ float sm[];
    float* xs      = sm;                      // [128 d][128 t]   16384 fl
    float* es      = xs + 16384;              // 2 x [16][128]     4096 fl
    float* enorm_s = es + 4096;               // [1024]            1024 fl
    unsigned long long* red_u =
        (unsigned long long*)(enorm_s + 1024);// [128][16] u64     4096 fl
    int*   idx_s   = (int*)(enorm_s + 1024 + 4096);   // [128]      128 fl
    float* As      = (float*)(idx_s + 128);   // [128] |x_t|^2      128 fl
    // total 25856 floats = 103424 bytes

    // ---- async stage: x tile (4096 f4), enorm (256 f4), E chunk 0 (512 f4)
    const float* xb = x + (size_t)b * DT_ + t0;
    #pragma unroll
    for (int r = 0; r < 16; r++) {
        int e = tid + (r << 8);             // 0..4095 float4 units
        int d = e >> 5, c4 = e & 31;
        CP_ASYNC16(smem_u32(xs + d * 128 + c4 * 4), xb + d * T_ + c4 * 4);
    }
    CP_ASYNC16(smem_u32(enorm_s + tid * 4), g_enorm + tid * 4);
    #pragma unroll
    for (int r = 0; r < 2; r++) {
        int e = tid + (r << 8);             // 0..511 float4 units
        int dd = e >> 5, c4 = e & 31;
        CP_ASYNC16(smem_u32(es + dd * 128 + c4 * 4), g_Et + dd * K_ + c4 * 4);
    }
    CP_COMMIT();

    // ---- init packed argmin slots while copies fly ----
    #pragma unroll
    for (int r = 0; r < 8; r++)
        red_u[tid + (r << 8)] = 0xFFFFFFFFFFFFFFFFull;

    CP_WAIT0();
    __syncthreads();

    // ---- per-token |x|^2 (fp64-exact -> fp32) ----
    if (tid < 128) {
        double a = 0.0;
        #pragma unroll 8
        for (int d = 0; d < 128; d++) {
            float xv = xs[d * 128 + tid];
            a += (double)xv * (double)xv;
        }
        As[tid] = (float)a;
    }
    __syncthreads();

    for (int ct = 0; ct < 8; ct++) {
        unsigned long long acc[8][4];
        #pragma unroll
        for (int i = 0; i < 8; i++)
            #pragma unroll
            for (int j = 0; j < 4; j++) acc[i][j] = 0ULL;

        for (int dc = 0; dc < 8; dc++) {
            const int q = ct * 8 + dc;
            float* eb = es + ((q & 1) << 11);          // holds chunk q

            // async-fill chunk q+1 into the other buffer (its last readers
            // finished before the sync that ended phase q-1)
            if (q + 1 < 64) {
                const int nq = q + 1, nct = nq >> 3, ndc = nq & 7;
                float* en = es + ((nq & 1) << 11);
                #pragma unroll
                for (int r = 0; r < 2; r++) {
                    int e = tid + (r << 8);
                    int dd = e >> 5, c4 = e & 31;
                    CP_ASYNC16(smem_u32(en + dd * 128 + c4 * 4),
                               g_Et + (ndc * 16 + dd) * K_ + nct * 128 + c4 * 4);
                }
            }
            CP_COMMIT();

            #pragma unroll
            for (int dd = 0; dd < 16; dd++) {
                const float4* ar =
                    (const float4*)&xs[(dc * 16 + dd) * 128 + ty * 8];
                float4 a0 = ar[0];
                float4 a1 = ar[1];
                const unsigned long long* brow =
                    (const unsigned long long*)&eb[dd * 128 + tx * 2];
                unsigned long long b0 = brow[0];       // codes 2tx,2tx+1
                unsigned long long b1 = brow[16];      // +32
                unsigned long long b2 = brow[32];      // +64
                unsigned long long b3 = brow[48];      // +96
                float av[8] = {a0.x, a0.y, a0.z, a0.w,
                               a1.x, a1.y, a1.z, a1.w};
                #pragma unroll
                for (int i = 0; i < 8; i++) {
                    unsigned long long ad;
                    PACK_DUP(ad, av[i]);
                    FMA_X2(acc[i][0], ad, b0);
                    FMA_X2(acc[i][1], ad, b1);
                    FMA_X2(acc[i][2], ad, b2);
                    FMA_X2(acc[i][3], ad, b3);
                }
            }
            CP_WAIT0();        // chunk q+1 landed
            __syncthreads();   // visible to all; eb free for reuse
        }

        // ---- fold into packed smem argmin, replicating reference rounding:
        //      dist = fl32( fl32(A + B_k) - 2*s_k );
        //      packed (valbits<<32 | col) min == min value, lowest index.
        #pragma unroll
        for (int i = 0; i < 8; i++) {
            const int t = ty * 8 + i;
            const float ai = As[t];
            unsigned long long best = 0xFFFFFFFFFFFFFFFFull;
            #pragma unroll
            for (int jp = 0; jp < 4; jp++) {
                float s0, s1;
                UNPACK_X2(s0, s1, acc[i][jp]);
                int col = ct * 128 + jp * 32 + tx * 2;
                float2 en2 = *(const float2*)&enorm_s[col];
                float v0 = __fadd_rn(__fadd_rn(ai, en2.x), -2.0f * s0);
                float v1 = __fadd_rn(__fadd_rn(ai, en2.y), -2.0f * s1);
                unsigned long long p0 =
                    ((unsigned long long)__float_as_uint(v0) << 32) |
                    (unsigned)col;
                unsigned long long p1 =
                    ((unsigned long long)__float_as_uint(v1) << 32) |
                    (unsigned)(col + 1);
                unsigned long long pm = p0 < p1 ? p0 : p1;
                if (pm < best) best = pm;
            }
            unsigned long long* slot = &red_u[t * 16 + tx];
            if (best < *slot) *slot = best;
        }
    }

    // ---- cross-thread argmin reduction (packed min) ----
    __syncthreads();
    if (tid < 128) {
        unsigned long long best = red_u[tid * 16];
        #pragma unroll
        for (int s = 1; s < 16; s++) {
            unsigned long long v = red_u[tid * 16 + s];
            if (v < best) best = v;
        }
        int bi = (int)(unsigned)best;
        idx_s[tid] = bi;
        out_idx[b * T_ + t0 + tid] = (float)bi;
        atomicAdd(&g_counts[bi], 1.0f);
    }
    __syncthreads();

    // ---- epilogue: straight-through output, dw scatter, loss ----
    const int t   = tid & 127;           // fixed per thread -> coalesced stores
    const int d0  = tid >> 7;
    const int myk = idx_s[t];
    const float* erow = E + myk * D_;
    float* ob = out_q + (size_t)b * DT_ + t0 + t;
    float* dwr = &g_dw[myk * D_];
    float lsum = 0.0f;
    #pragma unroll 4
    for (int r = 0; r < 64; r++) {
        int d = d0 + 2 * r;
        float xv = xs[d * 128 + t];
        float ev = erow[d];
        // replicate ref: q_st = xt + (quantized - xt), elementwise fp32
        ob[(size_t)d * T_] = __fadd_rn(xv, __fsub_rn(ev, xv));
        atomicAdd(&dwr[d], xv);
        float df = xv - ev;
        lsum += df * df;
    }
    #pragma unroll
    for (int o = 16; o > 0; o >>= 1)
        lsum += __shfl_xor_sync(0xffffffffu, lsum, o);
    if ((tid & 31) == 0) enorm_s[tid >> 5] = lsum;   // enorm_s free now
    __syncthreads();
    if (tid == 0) {
        float s = 0.0f;
        #pragma unroll
        for (int w = 0; w < 8; w++) s += enorm_s[w];
        atomicAdd(&g_loss, (double)s);
    }
}

// ---------------------------------------------------------------------------
// K3a: cluster-size EMA + Laplace smoothing + losses.  1 block, 1024 threads
// ---------------------------------------------------------------------------
__global__ void vq_stats(const float* __restrict__ ema_c,
                         float* __restrict__ out_loss) {
    int k = threadIdx.x;
    float c   = g_counts[k];
    float ema = ema_c[k];
    float hid = ema - (ema - c) * D1F;
    float avg = hid / D1F;
    __shared__ float sred[1024];
    sred[k] = avg;
    __syncthreads();
    for (int o = 512; o > 0; o >>= 1) {
        if (k < o) sred[k] += sred[k + o];
        __syncthreads();
    }
    float n = sred[0];
    g_cs[k] = (avg + EPSF) / (n + KEPSF) * n;
    if (k == 0) {
        float mse = (float)(g_loss / 16777216.0);
        out_loss[0] = 0.25f * mse;   // loss_commit
        out_loss[1] = mse;           // loss_vq
    }
}

// ---------------------------------------------------------------------------
// K3b: new_embeddings = avg_dw / cs.  512 blocks x 256
// ---------------------------------------------------------------------------
__global__ void vq_emb(const float* __restrict__ ema_dw,
                       float* __restrict__ out_emb) {
    int e = blockIdx.x * 256 + threadIdx.x;   // < 131072
    int k = e >> 7;
    float dwv = g_dw[e];
    float ema = ema_dw[e];
    float hid = ema - (ema - dwv) * D1F;
    float avg = hid / D1F;
    out_emb[e] = avg / g_cs[k];
}

// ---------------------------------------------------------------------------
extern "C" void kernel_launch(void* const* d_in, const int* in_sizes, int n_in,
                              void* d_out, int out_size) {
    const float* x      = (const float*)d_in[0];
    const float* E      = (const float*)d_in[1];
    const float* ema_dw = (const float*)d_in[2];
    const float* ema_c  = (const float*)d_in[3];
    float* out = (float*)d_out;

    void *p_dw = nullptr, *p_cnt = nullptr, *p_loss = nullptr;
    cudaGetSymbolAddress(&p_dw, g_dw);
    cudaGetSymbolAddress(&p_cnt, g_counts);
    cudaGetSymbolAddress(&p_loss, g_loss);
    cudaMemsetAsync(p_dw, 0, K_ * D_ * sizeof(float));
    cudaMemsetAsync(p_cnt, 0, K_ * sizeof(float));
    cudaMemsetAsync(p_loss, 0, sizeof(double));

    // vq_prep is idempotent; extra launches keep vq_main at ncu's -s 5 slot.
    vq_prep<<<K_, 128>>>(E);
    vq_prep<<<K_, 128>>>(E);
    vq_prep<<<K_, 128>>>(E);

    const int smem = 103424;
    cudaFuncSetAttribute(vq_main, cudaFuncAttributeMaxDynamicSharedMemorySize,
                         smem);
    dim3 grid(T_ / 128, B_);
    vq_main<<<grid, 256, smem>>>(x, E, out, out + IDX_OFF);

    vq_stats<<<1, 1024>>>(ema_c, out + LOSS_OFF);
    vq_emb<<<KD_ / 256, 256>>>(ema_dw, out + EMB_OFF);
}

// round 9
// speedup vs baseline: 1.3425x; 1.0134x over previous
#include <cuda_runtime.h>
#include <cuda_bf16.h>
#include <cstdint>

// ---------------------------------------------------------------------------
// VectorQuantizerEMA on GB300 (sm_103a) — mma.sync (HMMA) bf16 3-limb split.
// B=64, D=128, T=2048, K=1024, N=131072
//
// dist = fl32( fl32(|x|^2+|e|^2) - 2*(x.e) ), ties -> lowest index.
// x.e = s_hh (own fp32 accumulator; error profile == plain fp32 dot)
//     + s_small (mh, lh, hm, mm, hl cross-limb products), s = fl(add).
// tcgen05 is unavailable (harness PTX targets sm_103, not sm_103a), so the
// tensor path uses mma.sync.m16n8k16.row.col.f32.bf16.bf16.f32 (sm_80+).
// ---------------------------------------------------------------------------

#define B_   64
#define D_   128
#define T_   2048
#define K_   1024
#define NTOK 131072
#define DT_  (D_ * T_)
#define KD_  (K_ * D_)

#define LOSS_OFF    16777216
#define IDX_OFF     16777218
#define EMB_OFF     16908290

#define D1F   ((float)(1.0 - 0.99))
#define EPSF  1e-5f
#define KEPSF ((float)(1024 * 1e-5))

// -------- device-global scratch (static; no runtime allocation) --------
// A fragments: [limb 3][mt 8192][ks 8][lane 32] x uint4 (8 bf16/lane)  96MB
__device__ uint4  g_af[3 * 2097152];
// B fragments: [limb 3][nt 128][ks 8][lane 32] x uint2 (4 bf16/lane)  768KB
__device__ uint2  g_bfr[3 * 32768];
__device__ float  g_A[NTOK];          // fl32(exact |x_n|^2)
__device__ float  g_enorm[K_];        // fl32(exact |e_k|^2)
__device__ float  g_dw[KD_];
__device__ float  g_counts[K_];
__device__ float  g_cs[K_];
__device__ double g_loss;

// -------- helpers --------
__device__ __forceinline__ uint32_t smem_u32(const void* p) {
    return (uint32_t)__cvta_generic_to_shared(p);
}
#define CP_ASYNC16(dst_u32, src_ptr) \
    asm volatile("cp.async.cg.shared.global [%0], [%1], 16;" \
                 :: "r"(dst_u32), "l"(src_ptr) : "memory")
#define CP_COMMIT() asm volatile("cp.async.commit_group;" ::: "memory")
#define CP_WAIT0()  asm volatile("cp.async.wait_group 0;" ::: "memory")

// mma.sync m16n8k16 bf16 -> f32, A row-major, B col-major (PTX ISA layouts)
#define MMA16816(c, a, b)                                                      \
    asm("mma.sync.aligned.m16n8k16.row.col.f32.bf16.bf16.f32 "                 \
        "{%0,%1,%2,%3}, {%4,%5,%6,%7}, {%8,%9}, {%0,%1,%2,%3};"                \
        : "+f"((c)[0]), "+f"((c)[1]), "+f"((c)[2]), "+f"((c)[3])               \
        : "r"((a).x), "r"((a).y), "r"((a).z), "r"((a).w),                      \
          "r"((b).x), "r"((b).y))

// exact 3-way bf16 split (Sterbenz: both subtractions exact in fp32)
__device__ __forceinline__ void split3(float v, uint16_t& h, uint16_t& m,
                                       uint16_t& l) {
    __nv_bfloat16 bh = __float2bfloat16(v);
    float r1 = v - __bfloat162float(bh);
    __nv_bfloat16 bm = __float2bfloat16(r1);
    float r2 = r1 - __bfloat162float(bm);
    __nv_bfloat16 bl = __float2bfloat16(r2);
    h = __bfloat16_as_ushort(bh);
    m = __bfloat16_as_ushort(bm);
    l = __bfloat16_as_ushort(bl);
}

// ---------------------------------------------------------------------------
// |e|^2 (fp64 exact -> fp32). 1024 blocks x 128 threads.
// ---------------------------------------------------------------------------
__global__ void vq_enorm(const float* __restrict__ E) {
    int k = blockIdx.x;
    int d = threadIdx.x;
    float v = E[k * D_ + d];
    double s = (double)v * (double)v;
    #pragma unroll
    for (int o = 16; o > 0; o >>= 1) s += __shfl_xor_sync(0xffffffffu, s, o);
    __shared__ double ws[4];
    if ((d & 31) == 0) ws[d >> 5] = s;
    __syncthreads();
    if (d == 0) g_enorm[k] = (float)((ws[0] + ws[1]) + (ws[2] + ws[3]));
}

// ---------------------------------------------------------------------------
// E -> B fragments. 16 CTAs x 256 threads; CTA covers 64 codes (8 n-tiles).
// B frag (k=d, n=code): b0=(2t,g) b1=(2t+1,g) b2=(2t+8,g) b3=(2t+9,g).
// ---------------------------------------------------------------------------
__global__ void vq_efrag(const float* __restrict__ E) {
    const int c0 = blockIdx.x * 64;
    const int tid = threadIdx.x;
    #pragma unroll
    for (int i = 0; i < 8; i++) {
        int idx = tid + i * 256;           // [0,2048)
        int lane = idx & 31;
        int ks = (idx >> 5) & 7;
        int ntl = idx >> 8;                // 0..7
        int code = c0 + ntl * 8 + (lane >> 2);
        int t4 = lane & 3;
        uint32_t ph[2] = {0, 0}, pm[2] = {0, 0}, pl[2] = {0, 0};
        #pragma unroll
        for (int s = 0; s < 4; s++) {
            int d = ks * 16 + 2 * t4 + (s & 1) + ((s & 2) ? 8 : 0);
            uint16_t h, m, l;
            split3(E[code * D_ + d], h, m, l);
            int ri = s >> 1, sh = (s & 1) * 16;
            ph[ri] |= (uint32_t)h << sh;
            pm[ri] |= (uint32_t)m << sh;
            pl[ri] |= (uint32_t)l << sh;
        }
        int nt = c0 / 8 + ntl;
        int off = nt * 256 + ks * 32 + lane;
        g_bfr[0 * 32768 + off] = make_uint2(ph[0], ph[1]);
        g_bfr[1 * 32768 + off] = make_uint2(pm[0], pm[1]);
        g_bfr[2 * 32768 + off] = make_uint2(pl[0], pl[1]);
    }
}

// ---------------------------------------------------------------------------
// x -> A fragments + |x|^2. grid (16,64) x 256 threads.
// A frag (m=token,k=d): a0=(g,2t) a1=(g,2t+1) a2=(g+8,2t) a3=(g+8,2t+1)
//                       a4=(g,2t+8) a5=(g,2t+9) a6=(g+8,2t+8) a7=(g+8,2t+9)
// ---------------------------------------------------------------------------
__global__ __launch_bounds__(256) void vq_xprep(const float* __restrict__ x) {
    extern __shared__ float xs_t[];        // [128 tokens][129] padded
    const int b  = blockIdx.y;
    const int t0 = blockIdx.x * 128;
    const int tid = threadIdx.x;
    const int n0 = b * T_ + t0;

    const float* xb = x + (size_t)b * DT_ + t0;
    #pragma unroll
    for (int r = 0; r < 64; r++) {
        int e = tid + r * 256;
        int d = e >> 7, t = e & 127;
        xs_t[t * 129 + d] = xb[d * T_ + t];
    }
    __syncthreads();

    if (tid < 128) {
        double a = 0.0;
        #pragma unroll 8
        for (int d = 0; d < 128; d++) {
            float v = xs_t[tid * 129 + d];
            a += (double)v * (double)v;
        }
        g_A[n0 + tid] = (float)a;
    }

    const int gmt0 = n0 >> 4;
    #pragma unroll
    for (int i = 0; i < 8; i++) {
        int idx = tid + i * 256;           // [0,2048)
        int lane = idx & 31;
        int ks = (idx >> 5) & 7;
        int mt = idx >> 8;                 // 0..7
        int g = lane >> 2, t4 = lane & 3;
        uint32_t ph[4] = {0,0,0,0}, pm[4] = {0,0,0,0}, pl[4] = {0,0,0,0};
        #pragma unroll
        for (int s = 0; s < 8; s++) {
            int row = mt * 16 + g + ((s & 2) ? 8 : 0);
            int col = ks * 16 + 2 * t4 + (s & 1) + ((s & 4) ? 8 : 0);
            uint16_t h, m, l;
            split3(xs_t[row * 129 + col], h, m, l);
            int ri = s >> 1, sh = (s & 1) * 16;
            ph[ri] |= (uint32_t)h << sh;
            pm[ri] |= (uint32_t)m << sh;
            pl[ri] |= (uint32_t)l << sh;
        }
        size_t off = (size_t)(gmt0 + mt) * 256 + ks * 32 + lane;
        g_af[0 * 2097152 + off] = make_uint4(ph[0], ph[1], ph[2], ph[3]);
        g_af[1 * 2097152 + off] = make_uint4(pm[0], pm[1], pm[2], pm[3]);
        g_af[2 * 2097152 + off] = make_uint4(pl[0], pl[1], pl[2], pl[3]);
    }
}

// ---------------------------------------------------------------------------
// Main kernel: 1024 CTAs x 256 threads (8 warps), 200704B dynamic smem.
// CTA: 128 tokens; A limbs resident (96KB); 16 passes of 64 codes, B 48KB
// double-buffered via cp.async. Warp (wr=wid>>1, wc=wid&1): 32 tok x 32 codes.
// ---------------------------------------------------------------------------
struct TcSmem {
    unsigned long long wcmin[256];   // [128 tokens][2 wc]
    int   idx_s[128];
    float lred[8];
};

__global__ __launch_bounds__(256, 1) void vq_tc(
    const float* __restrict__ x,
    const float* __restrict__ E,
    float* __restrict__ out_q,
    float* __restrict__ out_idx)
{
    extern __shared__ char dynb[];   // A frags 98304 | B 2x49152 | enorm 4096
    __shared__ TcSmem ss;
    float* enorm_s = (float*)(dynb + 196608);

    const int bx = blockIdx.x;
    const int n0 = bx * 128;
    const int tid = threadIdx.x;
    const int lane = tid & 31;
    const int wid = tid >> 5;
    const int wr = wid >> 1, wc = wid & 1;
    const int g = lane >> 2, t4 = lane & 3;

    // ---- stage A frags (96KB), enorm, B pass 0 ----
    #pragma unroll
    for (int j = 0; j < 24; j++) {
        int rem = tid + (j & 7) * 256;     // [0,2048) u4 within limb
        int limb = j >> 3;
        CP_ASYNC16(smem_u32(dynb) + (uint32_t)((limb * 2048 + rem) << 4),
                   g_af + (size_t)limb * 2097152 + (size_t)bx * 2048 + rem);
    }
    CP_ASYNC16(smem_u32(enorm_s) + (uint32_t)(tid << 4), g_enorm + tid * 4);
    #pragma unroll
    for (int j = 0; j < 12; j++) {
        int rem4 = tid + (j & 3) * 256;    // [0,1024) u4 within limb slice
        int limb = j >> 2;
        CP_ASYNC16(smem_u32(dynb) + (uint32_t)(98304 + limb * 16384 + (rem4 << 4)),
                   (const uint4*)g_bfr + limb * 16384 + rem4);
    }
    CP_COMMIT();
    CP_WAIT0();
    __syncthreads();

    // per-thread token rows: slot = mt*2+h -> token n0 + wr*32 + mt*16 + h*8 + g
    float Atok[4];
    #pragma unroll
    for (int s = 0; s < 4; s++)
        Atok[s] = g_A[n0 + wr * 32 + (s >> 1) * 16 + (s & 1) * 8 + g];

    unsigned long long run[4] = {~0ull, ~0ull, ~0ull, ~0ull};
    float accA[2][4][4], accS[2][4][4];

    #pragma unroll 1
    for (int p = 0; p < 16; p++) {
        const char* bb = dynb + 98304 + (p & 1) * 49152;

        if (p < 15) {
            const int np = p + 1;
            uint32_t dst0 = smem_u32(dynb) + 98304u + (uint32_t)((np & 1) * 49152);
            #pragma unroll
            for (int j = 0; j < 12; j++) {
                int rem4 = tid + (j & 3) * 256;
                int limb = j >> 2;
                CP_ASYNC16(dst0 + (uint32_t)(limb * 16384 + (rem4 << 4)),
                           (const uint4*)g_bfr + limb * 16384 + np * 1024 + rem4);
            }
            CP_COMMIT();
        }

        #pragma unroll
        for (int mt = 0; mt < 2; mt++)
            #pragma unroll
            for (int nt = 0; nt < 4; nt++)
                #pragma unroll
                for (int q = 0; q < 4; q++) {
                    accA[mt][nt][q] = 0.0f;
                    accS[mt][nt][q] = 0.0f;
                }

        #pragma unroll 2
        for (int ks = 0; ks < 8; ks++) {
            uint4 Af[3][2];
            uint2 Bf[3][4];
            #pragma unroll
            for (int limb = 0; limb < 3; limb++)
                #pragma unroll
                for (int mt = 0; mt < 2; mt++)
                    Af[limb][mt] = *(const uint4*)(dynb +
                        ((limb * 2048 + (wr * 2 + mt) * 256 + ks * 32 + lane) << 4));
            #pragma unroll
            for (int limb = 0; limb < 3; limb++)
                #pragma unroll
                for (int nt = 0; nt < 4; nt++)
                    Bf[limb][nt] = *(const uint2*)(bb +
                        ((limb * 2048 + (wc * 4 + nt) * 256 + ks * 32 + lane) << 3));
            #pragma unroll
            for (int mt = 0; mt < 2; mt++)
                #pragma unroll
                for (int nt = 0; nt < 4; nt++) {
                    MMA16816(accA[mt][nt], Af[0][mt], Bf[0][nt]);   // h*H
                    MMA16816(accS[mt][nt], Af[1][mt], Bf[0][nt]);   // m*H
                    MMA16816(accS[mt][nt], Af[2][mt], Bf[0][nt]);   // l*H
                    MMA16816(accS[mt][nt], Af[0][mt], Bf[1][nt]);   // h*M
                    MMA16816(accS[mt][nt], Af[1][mt], Bf[1][nt]);   // m*M
                    MMA16816(accS[mt][nt], Af[0][mt], Bf[2][nt]);   // h*L
                }
        }

        // fold pass into running packed argmin
        #pragma unroll
        for (int mt = 0; mt < 2; mt++)
            #pragma unroll
            for (int h = 0; h < 2; h++) {
                const int slot = mt * 2 + h;
                const float ai = Atok[slot];
                #pragma unroll
                for (int nt = 0; nt < 4; nt++) {
                    int col = p * 64 + wc * 32 + nt * 8 + t4 * 2;
                    float2 en2 = *(const float2*)&enorm_s[col];
                    float s0 = __fadd_rn(accA[mt][nt][h * 2],
                                         accS[mt][nt][h * 2]);
                    float s1 = __fadd_rn(accA[mt][nt][h * 2 + 1],
                                         accS[mt][nt][h * 2 + 1]);
                    float v0 = __fmaf_rn(-2.0f, s0, __fadd_rn(ai, en2.x));
                    float v1 = __fmaf_rn(-2.0f, s1, __fadd_rn(ai, en2.y));
                    unsigned long long p0 =
                        ((unsigned long long)__float_as_uint(v0) << 32) |
                        (unsigned)col;
                    unsigned long long p1 =
                        ((unsigned long long)__float_as_uint(v1) << 32) |
                        (unsigned)(col + 1);
                    if (p0 < run[slot]) run[slot] = p0;
                    if (p1 < run[slot]) run[slot] = p1;
                }
            }

        if (p < 15) CP_WAIT0();
        __syncthreads();
    }

    // ---- cross-lane + cross-warp argmin ----
    #pragma unroll
    for (int s = 0; s < 4; s++) {
        unsigned long long r = run[s];
        unsigned long long o = __shfl_xor_sync(0xffffffffu, r, 1);
        if (o < r) r = o;
        o = __shfl_xor_sync(0xffffffffu, r, 2);
        if (o < r) r = o;
        if (t4 == 0) {
            int tokloc = wr * 32 + (s >> 1) * 16 + (s & 1) * 8 + g;
            ss.wcmin[tokloc * 2 + wc] = r;
        }
    }
    __syncthreads();
    if (tid < 128) {
        unsigned long long a = ss.wcmin[tid * 2];
        unsigned long long c = ss.wcmin[tid * 2 + 1];
        if (c < a) a = c;
        int bi = (int)(unsigned)a;
        ss.idx_s[tid] = bi;
        out_idx[n0 + tid] = (float)bi;
        atomicAdd(&g_counts[bi], 1.0f);
    }
    __syncthreads();

    // ---- out / dw / loss epilogue ----
    {
        const int b  = bx >> 4;
        const int t0 = (bx & 15) << 7;
        const int t  = tid & 127;
        const int d0 = tid >> 7;
        const int myk = ss.idx_s[t];
        const float* erow = E + myk * D_;
        const float* xcol = x + (size_t)b * DT_ + t0 + t;
        float* ob = out_q + (size_t)b * DT_ + t0 + t;
        float* dwr = &g_dw[myk * D_];
        float lsum = 0.0f;
        #pragma unroll 4
        for (int r = 0; r < 64; r++) {
            int d = d0 + 2 * r;
            float xv = xcol[(size_t)d * T_];
            float ev = erow[d];
            ob[(size_t)d * T_] = __fadd_rn(xv, __fsub_rn(ev, xv));
            atomicAdd(&dwr[d], xv);
            float df = xv - ev;
            lsum += df * df;
        }
        #pragma unroll
        for (int o = 16; o > 0; o >>= 1)
            lsum += __shfl_xor_sync(0xffffffffu, lsum, o);
        if ((tid & 31) == 0) ss.lred[tid >> 5] = lsum;
        __syncthreads();
        if (tid == 0) {
            float s = 0.0f;
            #pragma unroll
            for (int w = 0; w < 8; w++) s += ss.lred[w];
            atomicAdd(&g_loss, (double)s);
        }
    }
}

// ---------------------------------------------------------------------------
// Stats + new embeddings
// ---------------------------------------------------------------------------
__global__ void vq_stats(const float* __restrict__ ema_c,
                         float* __restrict__ out_loss) {
    int k = threadIdx.x;
    float c   = g_counts[k];
    float ema = ema_c[k];
    float hid = ema - (ema - c) * D1F;
    float avg = hid / D1F;
    __shared__ float sred[1024];
    sred[k] = avg;
    __syncthreads();
    for (int o = 512; o > 0; o >>= 1) {
        if (k < o) sred[k] += sred[k + o];
        __syncthreads();
    }
    float n = sred[0];
    g_cs[k] = (avg + EPSF) / (n + KEPSF) * n;
    if (k == 0) {
        float mse = (float)(g_loss / 16777216.0);
        out_loss[0] = 0.25f * mse;
        out_loss[1] = mse;
    }
}

__global__ void vq_emb(const float* __restrict__ ema_dw,
                       float* __restrict__ out_emb) {
    int e = blockIdx.x * 256 + threadIdx.x;
    int k = e >> 7;
    float dwv = g_dw[e];
    float ema = ema_dw[e];
    float hid = ema - (ema - dwv) * D1F;
    float avg = hid / D1F;
    out_emb[e] = avg / g_cs[k];
}

// ---------------------------------------------------------------------------
extern "C" void kernel_launch(void* const* d_in, const int* in_sizes, int n_in,
                              void* d_out, int out_size) {
    const float* x      = (const float*)d_in[0];
    const float* E      = (const float*)d_in[1];
    const float* ema_dw = (const float*)d_in[2];
    const float* ema_c  = (const float*)d_in[3];
    float* out = (float*)d_out;

    void *p_dw = nullptr, *p_cnt = nullptr, *p_loss = nullptr;
    cudaGetSymbolAddress(&p_dw, g_dw);
    cudaGetSymbolAddress(&p_cnt, g_counts);
    cudaGetSymbolAddress(&p_loss, g_loss);
    cudaMemsetAsync(p_dw, 0, KD_ * sizeof(float));
    cudaMemsetAsync(p_cnt, 0, K_ * sizeof(float));
    cudaMemsetAsync(p_loss, 0, sizeof(double));

    vq_enorm<<<K_, 128>>>(E);
    vq_efrag<<<16, 256>>>(E);

    cudaFuncSetAttribute(vq_xprep, cudaFuncAttributeMaxDynamicSharedMemorySize,
                         128 * 129 * 4);
    dim3 pgrid(16, 64);
    vq_xprep<<<pgrid, 256, 128 * 129 * 4>>>(x);

    const int smem = 200704;   // 98304 A + 2*49152 B + 4096 enorm
    cudaFuncSetAttribute(vq_tc, cudaFuncAttributeMaxDynamicSharedMemorySize,
                         smem);
    vq_tc<<<1024, 256, smem>>>(x, E, out, out + IDX_OFF);

    vq_stats<<<1, 1024>>>(ema_c, out + LOSS_OFF);
    vq_emb<<<KD_ / 256, 256>>>(ema_dw, out + EMB_OFF);
}